// round 2
// baseline (speedup 1.0000x reference)
#include <cuda_runtime.h>
#include <math.h>

#define BB 8
#define TT 1024
#define DD 128
#define UU 2048
#define OUTF (DD + UU)
#define NCTA 128
#define COLS 16
#define NTHR 256

// SMEM layout (floats)
#define W_FLOATS   (UU * COLS)   // 32768  w_res slice [2048][16]
#define S_FLOATS   (UU * BB)     // 16384  state        [2048][8]
#define WI_FLOATS  (DD * COLS)   // 2048   w_in slice   [128][16]
#define X_FLOATS   (BB * DD)     // 1024   x_t          [8][128]
#define BI_FLOATS  16
#define RED_ULL    (64 * 32)     // reduction buffer [64 outputs][32 kslices] f32x2
#define SMEM_FLOATS (W_FLOATS + S_FLOATS + WI_FLOATS + X_FLOATS + BI_FLOATS + RED_ULL * 2)
#define SMEM_BYTES  (SMEM_FLOATS * 4)   // 225344 B < 227 KB max dyn smem

__device__ float g_state[2][UU * BB];     // ping-pong state, layout [k][b]
__device__ unsigned g_bar_count;          // zero-init
__device__ unsigned g_bar_gen;            // monotone across replays (read-before-arrive)

__device__ __forceinline__ void cp16(unsigned dst, const void* src) {
    asm volatile("cp.async.cg.shared.global [%0], [%1], 16;" :: "r"(dst), "l"(src));
}
__device__ __forceinline__ void cp_commit() { asm volatile("cp.async.commit_group;"); }
template <int N>
__device__ __forceinline__ void cp_wait() {
    asm volatile("cp.async.wait_group %0;" :: "n"(N));
}
// packed fp32x2 FMA — ptxas never emits this from C++; via PTX it doubles fp32 MAC rate
__device__ __forceinline__ void ffma2(unsigned long long& acc, unsigned long long a,
                                      unsigned long long b) {
    asm("fma.rn.f32x2 %0, %1, %2, %0;" : "+l"(acc) : "l"(a), "l"(b));
}
__device__ __forceinline__ unsigned long long dup2(float x) {
    unsigned long long r;
    unsigned xi = __float_as_uint(x);
    asm("mov.b64 %0, {%1, %1};" : "=l"(r) : "r"(xi));
    return r;
}

// Grid-wide barrier: all 128 CTAs are co-resident (1 CTA/SM via SMEM footprint).
__device__ __forceinline__ void grid_barrier() {
    __syncthreads();
    if (threadIdx.x == 0) {
        __threadfence();  // release own stores (also CCTL.IVALL -> own L1 clean)
        unsigned gen;
        asm volatile("ld.acquire.gpu.u32 %0, [%1];" : "=r"(gen) : "l"(&g_bar_gen));
        if (atomicAdd(&g_bar_count, 1) == NCTA - 1) {
            g_bar_count = 0;  // only touched again after gen release below
            asm volatile("st.release.gpu.u32 [%0], %1;" :: "l"(&g_bar_gen), "r"(gen + 1)
                         : "memory");
        } else {
            unsigned cur;
            do {
                asm volatile("ld.acquire.gpu.u32 %0, [%1];" : "=r"(cur) : "l"(&g_bar_gen));
                if (cur != gen) break;
                __nanosleep(40);
            } while (true);
        }
    }
    __syncthreads();
}

template <int ITERS>
__device__ __forceinline__ void dot_block(const float* __restrict__ s_sh,
                                          const float* __restrict__ w_sh, int kbase,
                                          int b0, int j0, unsigned long long acc[2][4]) {
#pragma unroll 8
    for (int i = 0; i < ITERS; ++i) {
        int k = kbase + i * 32;  // interleaved k-slices: conflict-free SMEM rows in a warp
        float2 s01 = *(const float2*)(s_sh + k * 8 + b0);
        ulonglong2 wA = *(const ulonglong2*)(w_sh + k * 16 + j0);
        ulonglong2 wB = *(const ulonglong2*)(w_sh + k * 16 + j0 + 4);
        unsigned long long d0 = dup2(s01.x);
        unsigned long long d1 = dup2(s01.y);
        ffma2(acc[0][0], wA.x, d0); ffma2(acc[0][1], wA.y, d0);
        ffma2(acc[0][2], wB.x, d0); ffma2(acc[0][3], wB.y, d0);
        ffma2(acc[1][0], wA.x, d1); ffma2(acc[1][1], wA.y, d1);
        ffma2(acc[1][2], wB.x, d1); ffma2(acc[1][3], wB.y, d1);
    }
}

__global__ void __launch_bounds__(NTHR, 1)
esn_kernel(const float* __restrict__ inputs, const float* __restrict__ w_in_g,
           const float* __restrict__ b_in_g, const float* __restrict__ w_res_g,
           float* __restrict__ out) {
    extern __shared__ float smem[];
    float* w_sh  = smem;                    // [2048][16]
    float* s_sh  = w_sh + W_FLOATS;         // [2048][8]
    float* wi_sh = s_sh + S_FLOATS;         // [128][16]
    float* x_sh  = wi_sh + WI_FLOATS;       // [8][128]
    float* bi_sh = x_sh + X_FLOATS;         // [16]
    unsigned long long* red = (unsigned long long*)(bi_sh + BI_FLOATS);  // [64][32]

    const int tid = threadIdx.x;
    const int cta = blockIdx.x;
    const int col0 = cta * COLS;

    // Stage w_res slice [2048 x 16] once (16 MB chip-wide from HBM, ~2 us)
    for (int r = tid; r < UU; r += NTHR) {
        const float4* src = (const float4*)(w_res_g + (size_t)r * UU + col0);
        float4* dst = (float4*)(w_sh + r * COLS);
        dst[0] = src[0]; dst[1] = src[1]; dst[2] = src[2]; dst[3] = src[3];
    }
    for (int r = tid; r < DD; r += NTHR) {
        const float4* src = (const float4*)(w_in_g + (size_t)r * UU + col0);
        float4* dst = (float4*)(wi_sh + r * COLS);
        dst[0] = src[0]; dst[1] = src[1]; dst[2] = src[2]; dst[3] = src[3];
    }
    if (tid < COLS) bi_sh[tid] = b_in_g[col0 + tid];

    // Zero initial state (buffer 0); buffer 1 fully overwritten at t=0.
    for (int i = cta * NTHR + tid; i < UU * BB; i += NCTA * NTHR) g_state[0][i] = 0.0f;

    grid_barrier();

    // Thread decomposition: 32 k-slices x (4 b-pairs x 2 j-groups)
    const int ks = tid >> 3;            // 0..31 (k = ks mod 32, interleaved)
    const int o = tid & 7;
    const int b0 = (o >> 1) << 1;       // 0,2,4,6
    const int j0 = (o & 1) << 3;        // 0 or 8
    const unsigned s_base = (unsigned)__cvta_generic_to_shared(s_sh);
    const unsigned x_base = (unsigned)__cvta_generic_to_shared(x_sh);

    int cur = 0;
    for (int t = 0; t < TT; ++t) {
        const float* sg = g_state[cur];
        // group A: state chunk0 (k 0..1023) + x_t
#pragma unroll
        for (int i = 0; i < 8; ++i) {
            int idx = tid + i * NTHR;  // float4 index
            cp16(s_base + idx * 16, sg + idx * 4);
        }
        {
            int b = tid >> 5, q = tid & 31;
            cp16(x_base + tid * 16, inputs + ((size_t)(b * TT + t)) * DD + q * 4);
        }
        cp_commit();
        // group B: state chunk1 (k 1024..2047)
#pragma unroll
        for (int i = 0; i < 8; ++i) {
            int idx = 2048 + tid + i * NTHR;
            cp16(s_base + idx * 16, sg + idx * 4);
        }
        cp_commit();

        unsigned long long acc[2][4];
#pragma unroll
        for (int a1 = 0; a1 < 2; ++a1)
#pragma unroll
            for (int a2 = 0; a2 < 4; ++a2) acc[a1][a2] = 0ULL;

        cp_wait<1>();
        __syncthreads();
        dot_block<32>(s_sh, w_sh, ks, b0, j0, acc);            // chunk0 (chunk1 loads overlap)
        cp_wait<0>();
        __syncthreads();
        dot_block<32>(s_sh, w_sh, 1024 + ks, b0, j0, acc);     // chunk1

        // folded input projection x_t @ Win (K = 128)
#pragma unroll
        for (int i = 0; i < 4; ++i) {
            int k = ks + i * 32;
            unsigned long long d0 = dup2(x_sh[b0 * DD + k]);
            unsigned long long d1 = dup2(x_sh[(b0 + 1) * DD + k]);
            ulonglong2 wA = *(const ulonglong2*)(wi_sh + k * 16 + j0);
            ulonglong2 wB = *(const ulonglong2*)(wi_sh + k * 16 + j0 + 4);
            ffma2(acc[0][0], wA.x, d0); ffma2(acc[0][1], wA.y, d0);
            ffma2(acc[0][2], wB.x, d0); ffma2(acc[0][3], wB.y, d0);
            ffma2(acc[1][0], wA.x, d1); ffma2(acc[1][1], wA.y, d1);
            ffma2(acc[1][2], wB.x, d1); ffma2(acc[1][3], wB.y, d1);
        }

        // k-split reduction via SMEM
#pragma unroll
        for (int bi = 0; bi < 2; ++bi)
#pragma unroll
            for (int pi = 0; pi < 4; ++pi) {
                int og = (b0 + bi) * 8 + ((j0 >> 1) + pi);
                red[og * 32 + ks] = acc[bi][pi];
            }
        __syncthreads();

        if (tid < 64) {
            int b = tid >> 3, p = tid & 7;
            const float2* rp = (const float2*)(red + tid * 32);
            float v0 = 0.f, v1 = 0.f;
#pragma unroll
            for (int i = 0; i < 32; ++i) { v0 += rp[i].x; v1 += rp[i].y; }
            int c0 = col0 + 2 * p;
            float pre0 = v0 + bi_sh[2 * p];
            float pre1 = v1 + bi_sh[2 * p + 1];
            float so0 = s_sh[c0 * 8 + b];
            float so1 = s_sh[(c0 + 1) * 8 + b];
            float n0 = 0.5f * so0 + 0.5f * tanhf(pre0);
            float n1 = 0.5f * so1 + 0.5f * tanhf(pre1);
            float* sn = g_state[cur ^ 1];
            __stcg(sn + c0 * 8 + b, n0);           // L2-resident, no L1 staleness
            __stcg(sn + (c0 + 1) * 8 + b, n1);
            float2 ov;                             // PowerIndex: even col squared
            ov.x = n0 * n0;
            ov.y = n1;
            *(float2*)(out + ((size_t)(b * TT + t)) * OUTF + DD + c0) = ov;
        }

        grid_barrier();
        cur ^= 1;
    }
}

__global__ void copy_inputs_kernel(const float4* __restrict__ in, float* __restrict__ out) {
    int idx = blockIdx.x * blockDim.x + threadIdx.x;
    if (idx < BB * TT * DD / 4) {
        int bt = idx >> 5;  // 32 float4 per (b,t) row
        int q = idx & 31;
        float4 v = in[idx];
        *(float4*)(out + (size_t)bt * OUTF + q * 4) = v;
    }
}

extern "C" void kernel_launch(void* const* d_in, const int* in_sizes, int n_in,
                              void* d_out, int out_size) {
    const float* inputs = (const float*)d_in[0];
    const float* w_in   = (const float*)d_in[1];
    const float* b_in   = (const float*)d_in[2];
    const float* w_res  = (const float*)d_in[3];
    float* out = (float*)d_out;

    cudaFuncSetAttribute(esn_kernel, cudaFuncAttributeMaxDynamicSharedMemorySize, SMEM_BYTES);

    copy_inputs_kernel<<<(BB * TT * DD / 4 + 255) / 256, 256>>>((const float4*)inputs, out);
    esn_kernel<<<NCTA, NTHR, SMEM_BYTES>>>(inputs, w_in, b_in, w_res, out);
}

// round 3
// speedup vs baseline: 1.1839x; 1.1839x over previous
#include <cuda_runtime.h>
#include <math.h>

#define BB 8
#define TT 1024
#define DD 128
#define UU 2048
#define OUTF (DD + UU)
#define NCTA 128
#define COLS 16
#define NTHR 512
#define NWARP (NTHR / 32)

// SMEM layout (floats)
#define W_FLOATS   (UU * COLS)    // 32768  w_res slice [2048][16]
#define S_FLOATS   (UU * BB)      // 16384  state        [2048][8]
#define WI_FLOATS  (DD * COLS)    // 2048   w_in slice   [128][16]
#define BI_FLOATS  16
#define RED_PAIRS  (64 * NWARP)   // [16 warps][64 og] f32x2 partials
#define SMEM_FLOATS (W_FLOATS + S_FLOATS + WI_FLOATS + BI_FLOATS + RED_PAIRS * 2)
#define SMEM_BYTES  (SMEM_FLOATS * 4)   // 213 KB < 227 KB

__device__ float g_state[2][UU * BB];     // ping-pong state, layout [k][b]
__device__ unsigned g_bar_count;          // zero-init
__device__ unsigned g_bar_gen;            // monotone across replays (read-before-arrive)

__device__ __forceinline__ void cp16(unsigned dst, const void* src) {
    asm volatile("cp.async.cg.shared.global [%0], [%1], 16;" :: "r"(dst), "l"(src));
}
__device__ __forceinline__ void cp_commit() { asm volatile("cp.async.commit_group;"); }
template <int N>
__device__ __forceinline__ void cp_wait() {
    asm volatile("cp.async.wait_group %0;" :: "n"(N));
}
// packed fp32x2 FMA — ptxas never emits this from C++; doubles fp32 MAC rate
__device__ __forceinline__ void ffma2(unsigned long long& acc, unsigned long long a,
                                      unsigned long long b) {
    asm("fma.rn.f32x2 %0, %1, %2, %0;" : "+l"(acc) : "l"(a), "l"(b));
}
__device__ __forceinline__ unsigned long long dup2(float x) {
    unsigned long long r;
    unsigned xi = __float_as_uint(x);
    asm("mov.b64 %0, {%1, %1};" : "=l"(r) : "r"(xi));
    return r;
}
__device__ __forceinline__ unsigned long long padd2(unsigned long long a,
                                                    unsigned long long b) {
    unsigned long long r;
    asm("add.rn.f32x2 %0, %1, %2;" : "=l"(r) : "l"(a), "l"(b));
    return r;
}
__device__ __forceinline__ unsigned long long bfly2(unsigned long long v, int m) {
    unsigned lo = (unsigned)v, hi = (unsigned)(v >> 32);
    lo = __shfl_xor_sync(0xffffffffu, lo, m);
    hi = __shfl_xor_sync(0xffffffffu, hi, m);
    unsigned long long r;
    asm("mov.b64 %0, {%1, %2};" : "=l"(r) : "r"(lo), "r"(hi));
    return r;
}

// Grid-wide barrier: all 128 CTAs co-resident (1 CTA/SM via SMEM footprint).
__device__ __forceinline__ void grid_barrier() {
    __syncthreads();
    if (threadIdx.x == 0) {
        __threadfence();
        unsigned gen;
        asm volatile("ld.acquire.gpu.u32 %0, [%1];" : "=r"(gen) : "l"(&g_bar_gen));
        if (atomicAdd(&g_bar_count, 1) == NCTA - 1) {
            g_bar_count = 0;
            asm volatile("st.release.gpu.u32 [%0], %1;" :: "l"(&g_bar_gen), "r"(gen + 1)
                         : "memory");
        } else {
            unsigned cur;
            do {
                asm volatile("ld.acquire.gpu.u32 %0, [%1];" : "=r"(cur) : "l"(&g_bar_gen));
                if (cur != gen) break;
                __nanosleep(32);
            } while (true);
        }
    }
    __syncthreads();
}

// 16 k-iterations (k = kb + ks + 64*i), 8 FFMA2 each.
__device__ __forceinline__ void dot_block(const float* __restrict__ s_sh,
                                          const float* __restrict__ w_sh, int kb,
                                          int ks, int b0, int j0,
                                          unsigned long long acc[2][4]) {
#pragma unroll
    for (int i = 0; i < 16; ++i) {
        int k = kb + ks + i * 64;  // interleaved slices: conflict-free SMEM rows
        float2 s01 = *(const float2*)(s_sh + k * 8 + b0);
        ulonglong2 wA = *(const ulonglong2*)(w_sh + k * 16 + j0);
        ulonglong2 wB = *(const ulonglong2*)(w_sh + k * 16 + j0 + 4);
        unsigned long long d0 = dup2(s01.x);
        unsigned long long d1 = dup2(s01.y);
        ffma2(acc[0][0], wA.x, d0); ffma2(acc[0][1], wA.y, d0);
        ffma2(acc[0][2], wB.x, d0); ffma2(acc[0][3], wB.y, d0);
        ffma2(acc[1][0], wA.x, d1); ffma2(acc[1][1], wA.y, d1);
        ffma2(acc[1][2], wB.x, d1); ffma2(acc[1][3], wB.y, d1);
    }
}

__global__ void __launch_bounds__(NTHR, 1)
esn_kernel(const float* __restrict__ inputs, const float* __restrict__ w_in_g,
           const float* __restrict__ b_in_g, const float* __restrict__ w_res_g,
           float* __restrict__ out) {
    extern __shared__ float smem[];
    float* w_sh  = smem;                    // [2048][16]
    float* s_sh  = w_sh + W_FLOATS;         // [2048][8]
    float* wi_sh = s_sh + S_FLOATS;         // [128][16]
    float* bi_sh = wi_sh + WI_FLOATS;       // [16]
    unsigned long long* red = (unsigned long long*)(bi_sh + BI_FLOATS);  // [16w][64og]

    const int tid = threadIdx.x;
    const int cta = blockIdx.x;
    const int col0 = cta * COLS;

    // Stage w_res slice [2048 x 16] once
    for (int r = tid; r < UU; r += NTHR) {
        const float4* src = (const float4*)(w_res_g + (size_t)r * UU + col0);
        float4* dst = (float4*)(w_sh + r * COLS);
        dst[0] = src[0]; dst[1] = src[1]; dst[2] = src[2]; dst[3] = src[3];
    }
    for (int r = tid; r < DD; r += NTHR) {
        const float4* src = (const float4*)(w_in_g + (size_t)r * UU + col0);
        float4* dst = (float4*)(wi_sh + r * COLS);
        dst[0] = src[0]; dst[1] = src[1]; dst[2] = src[2]; dst[3] = src[3];
    }
    if (tid < COLS) bi_sh[tid] = b_in_g[col0 + tid];

    // Zero initial state (buffer 0); buffer 1 fully overwritten at t=0.
    for (int i = cta * NTHR + tid; i < UU * BB; i += NCTA * NTHR) g_state[0][i] = 0.0f;

    grid_barrier();

    // Decomposition: 64 k-slices x (4 b-pairs x 2 j-groups)
    const int ks = tid >> 3;            // 0..63
    const int o = tid & 7;
    const int b0 = (o >> 1) << 1;       // 0,2,4,6
    const int j0 = (o & 1) << 3;        // 0 or 8
    const int warp = tid >> 5;
    const int lane = tid & 31;
    const unsigned s_base = (unsigned)__cvta_generic_to_shared(s_sh);

    int cur = 0;
    for (int t = 0; t < TT; ++t) {
        const float* sg = g_state[cur];
        // state chunk0 (k 0..1023): 2048 float4
#pragma unroll
        for (int i = 0; i < 4; ++i) {
            int idx = tid + i * NTHR;
            cp16(s_base + idx * 16, sg + idx * 4);
        }
        cp_commit();
        // state chunk1 (k 1024..2047)
#pragma unroll
        for (int i = 0; i < 4; ++i) {
            int idx = 2048 + tid + i * NTHR;
            cp16(s_base + idx * 16, sg + idx * 4);
        }
        cp_commit();

        // x_t for this thread's (b0,b0+1) x (ks, ks+64): L2-resident, latency hidden by dot
        const float* xb0 = inputs + ((size_t)(b0 * TT + t)) * DD;
        const float* xb1 = inputs + ((size_t)((b0 + 1) * TT + t)) * DD;
        float x00 = __ldg(xb0 + ks);
        float x01 = __ldg(xb0 + ks + 64);
        float x10 = __ldg(xb1 + ks);
        float x11 = __ldg(xb1 + ks + 64);

        unsigned long long acc[2][4];
#pragma unroll
        for (int a1 = 0; a1 < 2; ++a1)
#pragma unroll
            for (int a2 = 0; a2 < 4; ++a2) acc[a1][a2] = 0ULL;

        cp_wait<1>();
        __syncthreads();
        dot_block(s_sh, w_sh, 0, ks, b0, j0, acc);       // chunk0 (chunk1 loads overlap)
        cp_wait<0>();
        __syncthreads();
        dot_block(s_sh, w_sh, 1024, ks, b0, j0, acc);    // chunk1

        // folded input projection x_t @ Win (K = 128), x from registers
#pragma unroll
        for (int i = 0; i < 2; ++i) {
            int k = ks + i * 64;
            unsigned long long d0 = dup2(i == 0 ? x00 : x01);
            unsigned long long d1 = dup2(i == 0 ? x10 : x11);
            ulonglong2 wA = *(const ulonglong2*)(wi_sh + k * 16 + j0);
            ulonglong2 wB = *(const ulonglong2*)(wi_sh + k * 16 + j0 + 4);
            ffma2(acc[0][0], wA.x, d0); ffma2(acc[0][1], wA.y, d0);
            ffma2(acc[0][2], wB.x, d0); ffma2(acc[0][3], wB.y, d0);
            ffma2(acc[1][0], wA.x, d1); ffma2(acc[1][1], wA.y, d1);
            ffma2(acc[1][2], wB.x, d1); ffma2(acc[1][3], wB.y, d1);
        }

        // In-register reduce over the warp's 4 k-slices (lane bits 3,4)
#pragma unroll
        for (int bi = 0; bi < 2; ++bi)
#pragma unroll
            for (int pi = 0; pi < 4; ++pi) {
                unsigned long long v = acc[bi][pi];
                v = padd2(v, bfly2(v, 8));
                v = padd2(v, bfly2(v, 16));
                acc[bi][pi] = v;
            }
        if (lane < 8) {
#pragma unroll
            for (int bi = 0; bi < 2; ++bi)
#pragma unroll
                for (int pi = 0; pi < 4; ++pi) {
                    int og = (b0 + bi) * 8 + ((j0 >> 1) + pi);
                    red[warp * 64 + og] = acc[bi][pi];
                }
        }
        __syncthreads();

        // Final reduce over 16 warps + epilogue
        if (tid < 64) {
            unsigned long long v = red[tid];
#pragma unroll
            for (int w = 1; w < NWARP; ++w) v = padd2(v, red[w * 64 + tid]);
            float v0 = __uint_as_float((unsigned)v);
            float v1 = __uint_as_float((unsigned)(v >> 32));
            int b = tid >> 3, p = tid & 7;
            int c0 = col0 + 2 * p;
            float pre0 = v0 + bi_sh[2 * p];
            float pre1 = v1 + bi_sh[2 * p + 1];
            float so0 = s_sh[c0 * 8 + b];
            float so1 = s_sh[(c0 + 1) * 8 + b];
            float n0 = 0.5f * so0 + 0.5f * tanhf(pre0);
            float n1 = 0.5f * so1 + 0.5f * tanhf(pre1);
            float* sn = g_state[cur ^ 1];
            __stcg(sn + c0 * 8 + b, n0);           // L2-resident, no L1 staleness
            __stcg(sn + (c0 + 1) * 8 + b, n1);
            float2 ov;                             // PowerIndex: even col squared
            ov.x = n0 * n0;
            ov.y = n1;
            *(float2*)(out + ((size_t)(b * TT + t)) * OUTF + DD + c0) = ov;
        }

        grid_barrier();
        cur ^= 1;
    }
}

__global__ void copy_inputs_kernel(const float4* __restrict__ in, float* __restrict__ out) {
    int idx = blockIdx.x * blockDim.x + threadIdx.x;
    if (idx < BB * TT * DD / 4) {
        int bt = idx >> 5;  // 32 float4 per (b,t) row
        int q = idx & 31;
        float4 v = in[idx];
        *(float4*)(out + (size_t)bt * OUTF + q * 4) = v;
    }
}

extern "C" void kernel_launch(void* const* d_in, const int* in_sizes, int n_in,
                              void* d_out, int out_size) {
    const float* inputs = (const float*)d_in[0];
    const float* w_in   = (const float*)d_in[1];
    const float* b_in   = (const float*)d_in[2];
    const float* w_res  = (const float*)d_in[3];
    float* out = (float*)d_out;

    cudaFuncSetAttribute(esn_kernel, cudaFuncAttributeMaxDynamicSharedMemorySize, SMEM_BYTES);

    copy_inputs_kernel<<<(BB * TT * DD / 4 + 255) / 256, 256>>>((const float4*)inputs, out);
    esn_kernel<<<NCTA, NTHR, SMEM_BYTES>>>(inputs, w_in, b_in, w_res, out);
}